// round 2
// baseline (speedup 1.0000x reference)
#include <cuda_runtime.h>
#include <cstdint>
#include <math.h>

// Problem constants
#define HID   2048
#define SEQ   2048
#define NB    2
#define NH    16
#define HD    128
#define TTOK  4096              // NB*SEQ tokens
#define W_ELEMS (HID*HID)       // 4,194,304

// ---------------------------------------------------------------------------
// Scratch (device globals — allocation-free per harness rules)
// ---------------------------------------------------------------------------
__device__ float       d_wscale[4];
__device__ float       d_partial[2048];
__device__ float       d_g[TTOK];
__device__ float       d_g2[TTOK];
__device__ signed char d_xq[(size_t)TTOK * HID];
__device__ signed char d_cq[(size_t)TTOK * HID];
__device__ signed char d_wq[(size_t)4 * W_ELEMS];
__device__ float       d_qb[(size_t)TTOK * HID];   // [B][NH][S][D]
__device__ float       d_kb[(size_t)TTOK * HID];
__device__ float       d_vb[(size_t)TTOK * HID];
__device__ float       d_ctx[(size_t)TTOK * HID];  // [t][HID]

// ---------------------------------------------------------------------------
// 1) weight scale: s = mean(|w|) + 1e-5  (two-stage deterministic reduction)
// ---------------------------------------------------------------------------
__global__ void row_abs_sum(const float* __restrict__ w, float* __restrict__ part) {
    __shared__ float red[256];
    int r = blockIdx.x;
    const float4* wr = (const float4*)(w + (size_t)r * HID);
    float s = 0.f;
    for (int i = threadIdx.x; i < HID / 4; i += 256) {
        float4 v = wr[i];
        s += fabsf(v.x) + fabsf(v.y) + fabsf(v.z) + fabsf(v.w);
    }
    red[threadIdx.x] = s;
    __syncthreads();
    for (int st = 128; st > 0; st >>= 1) {
        if (threadIdx.x < st) red[threadIdx.x] += red[threadIdx.x + st];
        __syncthreads();
    }
    if (threadIdx.x == 0) part[r] = red[0];
}

__global__ void finalize_scale(const float* __restrict__ part, int idx) {
    __shared__ float red[256];
    float s = 0.f;
    for (int i = threadIdx.x; i < 2048; i += 256) s += part[i];
    red[threadIdx.x] = s;
    __syncthreads();
    for (int st = 128; st > 0; st >>= 1) {
        if (threadIdx.x < st) red[threadIdx.x] += red[threadIdx.x + st];
        __syncthreads();
    }
    if (threadIdx.x == 0)
        d_wscale[idx] = red[0] / (float)W_ELEMS + 1e-5f;
}

// ---------------------------------------------------------------------------
// 2) ternary weight quantization: wq = clip(round(w/s), -1, 1)  (int8)
// ---------------------------------------------------------------------------
__global__ void quant_weight(const float* __restrict__ w, signed char* __restrict__ wq, int idx) {
    float s = d_wscale[idx];
    int i = blockIdx.x * blockDim.x + threadIdx.x;  // over W_ELEMS/4
    float4 v = ((const float4*)w)[i];
    char4 q;
    q.x = (signed char)fminf(fmaxf(rintf(v.x / s), -1.f), 1.f);
    q.y = (signed char)fminf(fmaxf(rintf(v.y / s), -1.f), 1.f);
    q.z = (signed char)fminf(fmaxf(rintf(v.z / s), -1.f), 1.f);
    q.w = (signed char)fminf(fmaxf(rintf(v.w / s), -1.f), 1.f);
    ((char4*)wq)[i] = q;
}

// ---------------------------------------------------------------------------
// 3) per-token int8 activation quantization: g = max|x|+eps; xq = clip(round(x*127/g))
// ---------------------------------------------------------------------------
__global__ void quant_act(const float* __restrict__ x, signed char* __restrict__ xq,
                          float* __restrict__ g) {
    __shared__ float red[256];
    __shared__ float gs;
    int t = blockIdx.x;
    const float4* xr = (const float4*)(x + (size_t)t * HID);
    float m = 0.f;
    for (int i = threadIdx.x; i < HID / 4; i += 256) {
        float4 v = xr[i];
        m = fmaxf(m, fmaxf(fmaxf(fabsf(v.x), fabsf(v.y)), fmaxf(fabsf(v.z), fabsf(v.w))));
    }
    red[threadIdx.x] = m;
    __syncthreads();
    for (int st = 128; st > 0; st >>= 1) {
        if (threadIdx.x < st) red[threadIdx.x] = fmaxf(red[threadIdx.x], red[threadIdx.x + st]);
        __syncthreads();
    }
    if (threadIdx.x == 0) {
        gs = red[0] + 1e-5f;
        g[t] = gs;
    }
    __syncthreads();
    float r = 127.0f / gs;
    char4* dst = (char4*)(xq + (size_t)t * HID);
    for (int i = threadIdx.x; i < HID / 4; i += 256) {
        float4 v = xr[i];
        char4 q;
        q.x = (signed char)fminf(fmaxf(rintf(v.x * r), -127.f), 127.f);
        q.y = (signed char)fminf(fmaxf(rintf(v.y * r), -127.f), 127.f);
        q.z = (signed char)fminf(fmaxf(rintf(v.z * r), -127.f), 127.f);
        q.w = (signed char)fminf(fmaxf(rintf(v.w * r), -127.f), 127.f);
        dst[i] = q;
    }
}

// ---------------------------------------------------------------------------
// 4) int8 GEMM via dp4a.  Y[t,o] = sum_i xq[t,i]*wq[o,i];  out = Y * g[t]/127 * s_w
//    BM=BN=128, BK=64 bytes, 256 threads, 8x8 outputs/thread (strided-16 mapping
//    so B-fragment shared loads are bank-conflict-free).
//    MODE 0: scatter to per-head layout [B][NH][S][D]   MODE 1: row-major [t][HID]
// ---------------------------------------------------------------------------
template <int MODE>
__global__ void __launch_bounds__(256) gemm8(
    const signed char* __restrict__ A, const signed char* __restrict__ W,
    const float* __restrict__ gact, int widx, float* __restrict__ out) {
    __shared__ int As[128][17];
    __shared__ int Bs[128][17];
    const int tid = threadIdx.x, tx = tid & 15, ty = tid >> 4;
    const int bm = blockIdx.y * 128, bn = blockIdx.x * 128;
    int acc[8][8];
#pragma unroll
    for (int i = 0; i < 8; i++)
#pragma unroll
        for (int j = 0; j < 8; j++) acc[i][j] = 0;

    const signed char* Ab = A + (size_t)bm * HID;
    const signed char* Wb = W + (size_t)bn * HID;

    for (int kt = 0; kt < HID; kt += 64) {
#pragma unroll
        for (int i = 0; i < 2; i++) {
            int l = tid + 256 * i;
            int r = l >> 2, c = l & 3;
            int4 va = *(const int4*)(Ab + (size_t)r * HID + kt + c * 16);
            int4 vb = *(const int4*)(Wb + (size_t)r * HID + kt + c * 16);
            As[r][c * 4 + 0] = va.x; As[r][c * 4 + 1] = va.y;
            As[r][c * 4 + 2] = va.z; As[r][c * 4 + 3] = va.w;
            Bs[r][c * 4 + 0] = vb.x; Bs[r][c * 4 + 1] = vb.y;
            Bs[r][c * 4 + 2] = vb.z; Bs[r][c * 4 + 3] = vb.w;
        }
        __syncthreads();
#pragma unroll
        for (int p = 0; p < 16; p++) {
            int a[8], b[8];
#pragma unroll
            for (int j = 0; j < 8; j++) {
                a[j] = As[ty + j * 16][p];
                b[j] = Bs[tx + j * 16][p];
            }
#pragma unroll
            for (int i = 0; i < 8; i++)
#pragma unroll
                for (int j = 0; j < 8; j++) acc[i][j] = __dp4a(a[i], b[j], acc[i][j]);
        }
        __syncthreads();
    }

    float sw = d_wscale[widx] * (1.0f / 127.0f);
#pragma unroll
    for (int i = 0; i < 8; i++) {
        int t = bm + ty + i * 16;
        float f = gact[t] * sw;
#pragma unroll
        for (int j = 0; j < 8; j++) {
            int o = bn + tx + j * 16;
            float v = (float)acc[i][j] * f;
            if (MODE == 0) {
                // [B][NH][S][D]
                out[(((size_t)(t >> 11) * NH + (o >> 7)) * SEQ + (t & 2047)) * HD + (o & 127)] = v;
            } else {
                out[(size_t)t * HID + o] = v;
            }
        }
    }
}

// ---------------------------------------------------------------------------
// 5) RoPE (in place on q and k, [B][NH][S][D]); double-precision angles
// ---------------------------------------------------------------------------
__global__ void rope_kernel(float* __restrict__ q, float* __restrict__ k) {
    int idx = blockIdx.x * 256 + threadIdx.x;   // NB*NH*SEQ*64 threads
    int i  = idx & 63;
    int s  = (idx >> 6) & 2047;
    int bh = idx >> 17;
    double inv = exp(-(double)i * (9.210340371976184 / 64.0));  // 10000^(-i/64)
    double ang = (double)s * inv;
    float c  = (float)cos(ang);
    float sn = (float)sin(ang);
    size_t off = ((size_t)bh * SEQ + s) * HD + i;
    float q1 = q[off], q2 = q[off + 64];
    q[off]      = q1 * c - q2 * sn;
    q[off + 64] = q2 * c + q1 * sn;
    float k1 = k[off], k2 = k[off + 64];
    k[off]      = k1 * c - k2 * sn;
    k[off + 64] = k2 * c + k1 * sn;
}

// ---------------------------------------------------------------------------
// 6) Flash attention (fp32, online softmax).
//    Block: 128 threads (4 warps), 16 queries (4/warp), 32-key tiles.
//    Scores: lane -> key, q broadcast from transposed smem (conflict-free).
//    PV: lane -> 4 output dims, p broadcast via per-warp smem staging.
// ---------------------------------------------------------------------------
__global__ void __launch_bounds__(128) attn_kernel(
    const float* __restrict__ Q, const float* __restrict__ K,
    const float* __restrict__ V, float* __restrict__ ctx) {
    __shared__ float qT[128][16];        // [d][query], pre-scaled
    __shared__ float kT[128][33];        // [d][key] (pad 33: conflict-free)
    __shared__ float vS[32][128];        // [key][d]
    __shared__ float pT[4][32][4];       // [warp][key][query]

    const int bh = blockIdx.y;           // 0..31
    const int q0 = blockIdx.x * 16;
    const int tid = threadIdx.x, w = tid >> 5, ln = tid & 31;
    const float scale = 0.08838834764831845f;  // 1/sqrt(128)

    const float* Qb = Q + ((size_t)bh * SEQ + q0) * HD;
    const float* Kb = K + (size_t)bh * SEQ * HD;
    const float* Vb = V + (size_t)bh * SEQ * HD;

    for (int idx = tid; idx < 16 * 128; idx += 128) {
        int qi = idx >> 7, d = idx & 127;
        qT[d][qi] = Qb[(size_t)qi * HD + d] * scale;
    }

    float m[4], l[4], acc[4][4];
#pragma unroll
    for (int qi = 0; qi < 4; qi++) {
        m[qi] = -1e30f; l[qi] = 0.f;
#pragma unroll
        for (int c = 0; c < 4; c++) acc[qi][c] = 0.f;
    }

    for (int kt = 0; kt < SEQ; kt += 32) {
        __syncthreads();
        for (int idx = tid; idx < 32 * 128; idx += 128) {
            int kk = idx >> 7, d = idx & 127;
            float kv = Kb[(size_t)(kt + kk) * HD + d];
            float vv = Vb[(size_t)(kt + kk) * HD + d];
            kT[d][kk] = kv;
            vS[kk][d] = vv;
        }
        __syncthreads();

        // scores: this warp's 4 queries vs lane's key
        float sc0 = 0.f, sc1 = 0.f, sc2 = 0.f, sc3 = 0.f;
#pragma unroll 16
        for (int d = 0; d < 128; d++) {
            float4 qv = *(const float4*)&qT[d][w * 4];
            float kv = kT[d][ln];
            sc0 += qv.x * kv; sc1 += qv.y * kv; sc2 += qv.z * kv; sc3 += qv.w * kv;
        }
        float sc[4] = {sc0, sc1, sc2, sc3};
        float p[4];
#pragma unroll
        for (int qi = 0; qi < 4; qi++) {
            float v = sc[qi];
            float tm = v;
#pragma unroll
            for (int o = 16; o > 0; o >>= 1) tm = fmaxf(tm, __shfl_xor_sync(0xffffffffu, tm, o));
            float nm = fmaxf(m[qi], tm);
            float pj = __expf(v - nm);
            float sum = pj;
#pragma unroll
            for (int o = 16; o > 0; o >>= 1) sum += __shfl_xor_sync(0xffffffffu, sum, o);
            float corr = __expf(m[qi] - nm);
            l[qi] = l[qi] * corr + sum;
            m[qi] = nm;
#pragma unroll
            for (int c = 0; c < 4; c++) acc[qi][c] *= corr;
            p[qi] = pj;
        }
        *(float4*)&pT[w][ln][0] = make_float4(p[0], p[1], p[2], p[3]);
        __syncwarp();

        // PV: lane owns dims 4*ln..4*ln+3
#pragma unroll 4
        for (int kk = 0; kk < 32; kk++) {
            float4 pv = *(const float4*)&pT[w][kk][0];
            float4 vv = *(const float4*)&vS[kk][ln * 4];
            acc[0][0] += pv.x * vv.x; acc[0][1] += pv.x * vv.y;
            acc[0][2] += pv.x * vv.z; acc[0][3] += pv.x * vv.w;
            acc[1][0] += pv.y * vv.x; acc[1][1] += pv.y * vv.y;
            acc[1][2] += pv.y * vv.z; acc[1][3] += pv.y * vv.w;
            acc[2][0] += pv.z * vv.x; acc[2][1] += pv.z * vv.y;
            acc[2][2] += pv.z * vv.z; acc[2][3] += pv.z * vv.w;
            acc[3][0] += pv.w * vv.x; acc[3][1] += pv.w * vv.y;
            acc[3][2] += pv.w * vv.z; acc[3][3] += pv.w * vv.w;
        }
    }

    // write ctx: [t][HID] with t = b*SEQ+query, col = h*128 + d
    int b = bh >> 4, h = bh & 15;
#pragma unroll
    for (int qi = 0; qi < 4; qi++) {
        int query = q0 + w * 4 + qi;
        size_t row = ((size_t)(b * SEQ + query)) * HID + h * HD;
        float invl = 1.0f / l[qi];
        *(float4*)&ctx[row + ln * 4] =
            make_float4(acc[qi][0] * invl, acc[qi][1] * invl,
                        acc[qi][2] * invl, acc[qi][3] * invl);
    }
}

// ---------------------------------------------------------------------------
// Launch
// ---------------------------------------------------------------------------
extern "C" void kernel_launch(void* const* d_in, const int* in_sizes, int n_in,
                              void* d_out, int out_size) {
    (void)in_sizes; (void)n_in; (void)out_size;
    const float* x   = (const float*)d_in[0];
    const float* W4[4] = {(const float*)d_in[1], (const float*)d_in[2],
                          (const float*)d_in[3], (const float*)d_in[4]};
    float* out = (float*)d_out;

    signed char *xq, *cq, *wq;
    float *g, *g2, *part, *qb, *kb, *vb, *ctx;
    cudaGetSymbolAddress((void**)&xq,  d_xq);
    cudaGetSymbolAddress((void**)&cq,  d_cq);
    cudaGetSymbolAddress((void**)&wq,  d_wq);
    cudaGetSymbolAddress((void**)&g,   d_g);
    cudaGetSymbolAddress((void**)&g2,  d_g2);
    cudaGetSymbolAddress((void**)&part, d_partial);
    cudaGetSymbolAddress((void**)&qb,  d_qb);
    cudaGetSymbolAddress((void**)&kb,  d_kb);
    cudaGetSymbolAddress((void**)&vb,  d_vb);
    cudaGetSymbolAddress((void**)&ctx, d_ctx);

    for (int i = 0; i < 4; i++) {
        row_abs_sum<<<2048, 256>>>(W4[i], part);
        finalize_scale<<<1, 256>>>(part, i);
        quant_weight<<<W_ELEMS / 4 / 256, 256>>>(W4[i], wq + (size_t)i * W_ELEMS, i);
    }

    quant_act<<<TTOK, 256>>>(x, xq, g);

    dim3 ggrid(HID / 128, TTOK / 128);
    gemm8<0><<<ggrid, 256>>>(xq, wq + (size_t)0 * W_ELEMS, g, 0, qb);
    gemm8<0><<<ggrid, 256>>>(xq, wq + (size_t)1 * W_ELEMS, g, 1, kb);
    gemm8<0><<<ggrid, 256>>>(xq, wq + (size_t)2 * W_ELEMS, g, 2, vb);

    rope_kernel<<<(NB * NH * SEQ * 64) / 256, 256>>>(qb, kb);

    attn_kernel<<<dim3(SEQ / 16, NB * NH), 128>>>(qb, kb, vb, ctx);

    quant_act<<<TTOK, 256>>>(ctx, cq, g2);
    gemm8<1><<<ggrid, 256>>>(cq, wq + (size_t)3 * W_ELEMS, g2, 3, out);
}

// round 3
// speedup vs baseline: 1.3254x; 1.3254x over previous
#include <cuda_runtime.h>
#include <cstdint>
#include <math.h>

// Problem constants
#define HID   2048
#define SEQ   2048
#define NB    2
#define NH    16
#define HD    128
#define TTOK  4096              // NB*SEQ tokens
#define W_ELEMS (HID*HID)       // 4,194,304

// ---------------------------------------------------------------------------
// Scratch (device globals — allocation-free per harness rules)
// ---------------------------------------------------------------------------
__device__ float       d_wscale[4];
__device__ float       d_partial[2048];
__device__ float       d_g[TTOK];
__device__ float       d_g2[TTOK];
__device__ signed char d_xq[(size_t)TTOK * HID];
__device__ signed char d_cq[(size_t)TTOK * HID];
__device__ signed char d_wq[(size_t)4 * W_ELEMS];
__device__ float       d_qb[(size_t)TTOK * HID];   // [B][NH][S][D]
__device__ float       d_kb[(size_t)TTOK * HID];
__device__ float       d_vb[(size_t)TTOK * HID];
__device__ float       d_ctx[(size_t)TTOK * HID];  // [t][HID]

// ---------------------------------------------------------------------------
// 1) weight scale: s = mean(|w|) + 1e-5  (two-stage deterministic reduction)
// ---------------------------------------------------------------------------
__global__ void row_abs_sum(const float* __restrict__ w, float* __restrict__ part) {
    __shared__ float red[256];
    int r = blockIdx.x;
    const float4* wr = (const float4*)(w + (size_t)r * HID);
    float s = 0.f;
    for (int i = threadIdx.x; i < HID / 4; i += 256) {
        float4 v = wr[i];
        s += fabsf(v.x) + fabsf(v.y) + fabsf(v.z) + fabsf(v.w);
    }
    red[threadIdx.x] = s;
    __syncthreads();
    for (int st = 128; st > 0; st >>= 1) {
        if (threadIdx.x < st) red[threadIdx.x] += red[threadIdx.x + st];
        __syncthreads();
    }
    if (threadIdx.x == 0) part[r] = red[0];
}

__global__ void finalize_scale(const float* __restrict__ part, int idx) {
    __shared__ float red[256];
    float s = 0.f;
    for (int i = threadIdx.x; i < 2048; i += 256) s += part[i];
    red[threadIdx.x] = s;
    __syncthreads();
    for (int st = 128; st > 0; st >>= 1) {
        if (threadIdx.x < st) red[threadIdx.x] += red[threadIdx.x + st];
        __syncthreads();
    }
    if (threadIdx.x == 0)
        d_wscale[idx] = red[0] / (float)W_ELEMS + 1e-5f;
}

// ---------------------------------------------------------------------------
// 2) ternary weight quantization: wq = clip(round(w/s), -1, 1)  (int8)
// ---------------------------------------------------------------------------
__global__ void quant_weight(const float* __restrict__ w, signed char* __restrict__ wq, int idx) {
    float s = d_wscale[idx];
    int i = blockIdx.x * blockDim.x + threadIdx.x;  // over W_ELEMS/4
    float4 v = ((const float4*)w)[i];
    char4 q;
    q.x = (signed char)fminf(fmaxf(rintf(v.x / s), -1.f), 1.f);
    q.y = (signed char)fminf(fmaxf(rintf(v.y / s), -1.f), 1.f);
    q.z = (signed char)fminf(fmaxf(rintf(v.z / s), -1.f), 1.f);
    q.w = (signed char)fminf(fmaxf(rintf(v.w / s), -1.f), 1.f);
    ((char4*)wq)[i] = q;
}

// ---------------------------------------------------------------------------
// 3) per-token int8 activation quantization
// ---------------------------------------------------------------------------
__global__ void quant_act(const float* __restrict__ x, signed char* __restrict__ xq,
                          float* __restrict__ g) {
    __shared__ float red[256];
    __shared__ float gs;
    int t = blockIdx.x;
    const float4* xr = (const float4*)(x + (size_t)t * HID);
    float m = 0.f;
    for (int i = threadIdx.x; i < HID / 4; i += 256) {
        float4 v = xr[i];
        m = fmaxf(m, fmaxf(fmaxf(fabsf(v.x), fabsf(v.y)), fmaxf(fabsf(v.z), fabsf(v.w))));
    }
    red[threadIdx.x] = m;
    __syncthreads();
    for (int st = 128; st > 0; st >>= 1) {
        if (threadIdx.x < st) red[threadIdx.x] = fmaxf(red[threadIdx.x], red[threadIdx.x + st]);
        __syncthreads();
    }
    if (threadIdx.x == 0) {
        gs = red[0] + 1e-5f;
        g[t] = gs;
    }
    __syncthreads();
    float r = 127.0f / gs;
    char4* dst = (char4*)(xq + (size_t)t * HID);
    for (int i = threadIdx.x; i < HID / 4; i += 256) {
        float4 v = xr[i];
        char4 q;
        q.x = (signed char)fminf(fmaxf(rintf(v.x * r), -127.f), 127.f);
        q.y = (signed char)fminf(fmaxf(rintf(v.y * r), -127.f), 127.f);
        q.z = (signed char)fminf(fmaxf(rintf(v.z * r), -127.f), 127.f);
        q.w = (signed char)fminf(fmaxf(rintf(v.w * r), -127.f), 127.f);
        dst[i] = q;
    }
}

// ---------------------------------------------------------------------------
// 4) int8 tensor-core GEMM (mma.sync m16n8k32 s8.s8.s32) — bit-exact vs dp4a.
//    BM=BN=BK=128, 256 threads (8 warps, 2x4), warp tile 64x32 (4x4 mma frags).
//    Smem rows padded to 36 words (144B): bank = (row*4 + col) mod 32, which
//    makes the STS.128 fill AND every fragment LDS conflict-free.
//    MODE 0: scatter to per-head layout [B][NH][S][D]   MODE 1: row-major
// ---------------------------------------------------------------------------
__device__ __forceinline__ void mma_s8(int* c, const uint32_t* a, const uint32_t* b) {
    asm volatile(
        "mma.sync.aligned.m16n8k32.row.col.s32.s8.s8.s32 "
        "{%0,%1,%2,%3}, {%4,%5,%6,%7}, {%8,%9}, {%0,%1,%2,%3};\n"
        : "+r"(c[0]), "+r"(c[1]), "+r"(c[2]), "+r"(c[3])
        : "r"(a[0]), "r"(a[1]), "r"(a[2]), "r"(a[3]), "r"(b[0]), "r"(b[1]));
}

template <int MODE>
__global__ void __launch_bounds__(256) gemm_imma(
    const signed char* __restrict__ A, const signed char* __restrict__ W,
    const float* __restrict__ gact, int widx, float* __restrict__ out) {
    __shared__ __align__(16) uint32_t As[128][36];
    __shared__ __align__(16) uint32_t Bs[128][36];
    const int tid = threadIdx.x;
    const int bm = blockIdx.y * 128, bn = blockIdx.x * 128;
    const int wid = tid >> 5, ln = tid & 31;
    const int wm = wid >> 2, wn = wid & 3;   // warp grid 2 (m) x 4 (n)

    int acc[4][4][4];
#pragma unroll
    for (int i = 0; i < 4; i++)
#pragma unroll
        for (int j = 0; j < 4; j++)
#pragma unroll
            for (int c = 0; c < 4; c++) acc[i][j][c] = 0;

    const int4* Ag = (const int4*)(A + (size_t)bm * HID);
    const int4* Wg = (const int4*)(W + (size_t)bn * HID);
    const int row_l = tid >> 3;   // + 32*i
    const int q = tid & 7;        // 16B chunk within 128B k-tile

    for (int kt = 0; kt < 16; kt++) {
#pragma unroll
        for (int i = 0; i < 4; i++) {
            int row = row_l + 32 * i;
            int4 va = Ag[(size_t)row * (HID / 16) + kt * 8 + q];
            int4 vb = Wg[(size_t)row * (HID / 16) + kt * 8 + q];
            *(int4*)&As[row][q * 4] = va;
            *(int4*)&Bs[row][q * 4] = vb;
        }
        __syncthreads();
#pragma unroll
        for (int ks = 0; ks < 4; ks++) {
            uint32_t af[4][4], bf[4][2];
            const int cb = ks * 8 + (ln & 3);
#pragma unroll
            for (int i = 0; i < 4; i++) {
                int r = wm * 64 + i * 16 + (ln >> 2);
                af[i][0] = As[r][cb];
                af[i][1] = As[r + 8][cb];
                af[i][2] = As[r][cb + 4];
                af[i][3] = As[r + 8][cb + 4];
            }
#pragma unroll
            for (int j = 0; j < 4; j++) {
                int r = wn * 32 + j * 8 + (ln >> 2);
                bf[j][0] = Bs[r][cb];
                bf[j][1] = Bs[r][cb + 4];
            }
#pragma unroll
            for (int i = 0; i < 4; i++)
#pragma unroll
                for (int j = 0; j < 4; j++) mma_s8(acc[i][j], af[i], bf[j]);
        }
        __syncthreads();
    }

    // epilogue: dequant = acc * g[token] * s_w / 127
    float sw = d_wscale[widx] * (1.0f / 127.0f);
    const int gr = ln >> 2, gc = (ln & 3) * 2;
#pragma unroll
    for (int i = 0; i < 4; i++) {
        int r0 = bm + wm * 64 + i * 16 + gr;
        int r1 = r0 + 8;
        float f0 = gact[r0] * sw;
        float f1 = gact[r1] * sw;
#pragma unroll
        for (int j = 0; j < 4; j++) {
            int col = bn + wn * 32 + j * 8 + gc;
            float2 v0 = make_float2(acc[i][j][0] * f0, acc[i][j][1] * f0);
            float2 v1 = make_float2(acc[i][j][2] * f1, acc[i][j][3] * f1);
            if (MODE == 0) {
                size_t o0 = (((size_t)(r0 >> 11) * NH + (col >> 7)) * SEQ + (r0 & 2047)) * HD + (col & 127);
                size_t o1 = (((size_t)(r1 >> 11) * NH + (col >> 7)) * SEQ + (r1 & 2047)) * HD + (col & 127);
                *(float2*)&out[o0] = v0;
                *(float2*)&out[o1] = v1;
            } else {
                *(float2*)&out[(size_t)r0 * HID + col] = v0;
                *(float2*)&out[(size_t)r1 * HID + col] = v1;
            }
        }
    }
}

// ---------------------------------------------------------------------------
// 5) RoPE (in place on q and k, [B][NH][S][D]); double-precision angles
// ---------------------------------------------------------------------------
__global__ void rope_kernel(float* __restrict__ q, float* __restrict__ k) {
    int idx = blockIdx.x * 256 + threadIdx.x;   // NB*NH*SEQ*64 threads
    int i  = idx & 63;
    int s  = (idx >> 6) & 2047;
    int bh = idx >> 17;
    double inv = exp(-(double)i * (9.210340371976184 / 64.0));  // 10000^(-i/64)
    double ang = (double)s * inv;
    float c  = (float)cos(ang);
    float sn = (float)sin(ang);
    size_t off = ((size_t)bh * SEQ + s) * HD + i;
    float q1 = q[off], q2 = q[off + 64];
    q[off]      = q1 * c - q2 * sn;
    q[off + 64] = q2 * c + q1 * sn;
    float k1 = k[off], k2 = k[off + 64];
    k[off]      = k1 * c - k2 * sn;
    k[off + 64] = k2 * c + k1 * sn;
}

// ---------------------------------------------------------------------------
// 6) Flash attention (fp32, online softmax). Unchanged this round.
// ---------------------------------------------------------------------------
__global__ void __launch_bounds__(128) attn_kernel(
    const float* __restrict__ Q, const float* __restrict__ K,
    const float* __restrict__ V, float* __restrict__ ctx) {
    __shared__ float qT[128][16];        // [d][query], pre-scaled
    __shared__ float kT[128][33];        // [d][key] (pad 33: conflict-free)
    __shared__ float vS[32][128];        // [key][d]
    __shared__ float pT[4][32][4];       // [warp][key][query]

    const int bh = blockIdx.y;           // 0..31
    const int q0 = blockIdx.x * 16;
    const int tid = threadIdx.x, w = tid >> 5, ln = tid & 31;
    const float scale = 0.08838834764831845f;  // 1/sqrt(128)

    const float* Qb = Q + ((size_t)bh * SEQ + q0) * HD;
    const float* Kb = K + (size_t)bh * SEQ * HD;
    const float* Vb = V + (size_t)bh * SEQ * HD;

    for (int idx = tid; idx < 16 * 128; idx += 128) {
        int qi = idx >> 7, d = idx & 127;
        qT[d][qi] = Qb[(size_t)qi * HD + d] * scale;
    }

    float m[4], l[4], acc[4][4];
#pragma unroll
    for (int qi = 0; qi < 4; qi++) {
        m[qi] = -1e30f; l[qi] = 0.f;
#pragma unroll
        for (int c = 0; c < 4; c++) acc[qi][c] = 0.f;
    }

    for (int kt = 0; kt < SEQ; kt += 32) {
        __syncthreads();
        for (int idx = tid; idx < 32 * 128; idx += 128) {
            int kk = idx >> 7, d = idx & 127;
            float kv = Kb[(size_t)(kt + kk) * HD + d];
            float vv = Vb[(size_t)(kt + kk) * HD + d];
            kT[d][kk] = kv;
            vS[kk][d] = vv;
        }
        __syncthreads();

        float sc0 = 0.f, sc1 = 0.f, sc2 = 0.f, sc3 = 0.f;
#pragma unroll 16
        for (int d = 0; d < 128; d++) {
            float4 qv = *(const float4*)&qT[d][w * 4];
            float kv = kT[d][ln];
            sc0 += qv.x * kv; sc1 += qv.y * kv; sc2 += qv.z * kv; sc3 += qv.w * kv;
        }
        float sc[4] = {sc0, sc1, sc2, sc3};
        float p[4];
#pragma unroll
        for (int qi = 0; qi < 4; qi++) {
            float v = sc[qi];
            float tm = v;
#pragma unroll
            for (int o = 16; o > 0; o >>= 1) tm = fmaxf(tm, __shfl_xor_sync(0xffffffffu, tm, o));
            float nm = fmaxf(m[qi], tm);
            float pj = __expf(v - nm);
            float sum = pj;
#pragma unroll
            for (int o = 16; o > 0; o >>= 1) sum += __shfl_xor_sync(0xffffffffu, sum, o);
            float corr = __expf(m[qi] - nm);
            l[qi] = l[qi] * corr + sum;
            m[qi] = nm;
#pragma unroll
            for (int c = 0; c < 4; c++) acc[qi][c] *= corr;
            p[qi] = pj;
        }
        *(float4*)&pT[w][ln][0] = make_float4(p[0], p[1], p[2], p[3]);
        __syncwarp();

#pragma unroll 4
        for (int kk = 0; kk < 32; kk++) {
            float4 pv = *(const float4*)&pT[w][kk][0];
            float4 vv = *(const float4*)&vS[kk][ln * 4];
            acc[0][0] += pv.x * vv.x; acc[0][1] += pv.x * vv.y;
            acc[0][2] += pv.x * vv.z; acc[0][3] += pv.x * vv.w;
            acc[1][0] += pv.y * vv.x; acc[1][1] += pv.y * vv.y;
            acc[1][2] += pv.y * vv.z; acc[1][3] += pv.y * vv.w;
            acc[2][0] += pv.z * vv.x; acc[2][1] += pv.z * vv.y;
            acc[2][2] += pv.z * vv.z; acc[2][3] += pv.z * vv.w;
            acc[3][0] += pv.w * vv.x; acc[3][1] += pv.w * vv.y;
            acc[3][2] += pv.w * vv.z; acc[3][3] += pv.w * vv.w;
        }
    }

    int b = bh >> 4, h = bh & 15;
#pragma unroll
    for (int qi = 0; qi < 4; qi++) {
        int query = q0 + w * 4 + qi;
        size_t row = ((size_t)(b * SEQ + query)) * HID + h * HD;
        float invl = 1.0f / l[qi];
        *(float4*)&ctx[row + ln * 4] =
            make_float4(acc[qi][0] * invl, acc[qi][1] * invl,
                        acc[qi][2] * invl, acc[qi][3] * invl);
    }
}

// ---------------------------------------------------------------------------
// Launch
// ---------------------------------------------------------------------------
extern "C" void kernel_launch(void* const* d_in, const int* in_sizes, int n_in,
                              void* d_out, int out_size) {
    (void)in_sizes; (void)n_in; (void)out_size;
    const float* x   = (const float*)d_in[0];
    const float* W4[4] = {(const float*)d_in[1], (const float*)d_in[2],
                          (const float*)d_in[3], (const float*)d_in[4]};
    float* out = (float*)d_out;

    signed char *xq, *cq, *wq;
    float *g, *g2, *part, *qb, *kb, *vb, *ctx;
    cudaGetSymbolAddress((void**)&xq,  d_xq);
    cudaGetSymbolAddress((void**)&cq,  d_cq);
    cudaGetSymbolAddress((void**)&wq,  d_wq);
    cudaGetSymbolAddress((void**)&g,   d_g);
    cudaGetSymbolAddress((void**)&g2,  d_g2);
    cudaGetSymbolAddress((void**)&part, d_partial);
    cudaGetSymbolAddress((void**)&qb,  d_qb);
    cudaGetSymbolAddress((void**)&kb,  d_kb);
    cudaGetSymbolAddress((void**)&vb,  d_vb);
    cudaGetSymbolAddress((void**)&ctx, d_ctx);

    for (int i = 0; i < 4; i++) {
        row_abs_sum<<<2048, 256>>>(W4[i], part);
        finalize_scale<<<1, 256>>>(part, i);
        quant_weight<<<W_ELEMS / 4 / 256, 256>>>(W4[i], wq + (size_t)i * W_ELEMS, i);
    }

    quant_act<<<TTOK, 256>>>(x, xq, g);

    dim3 ggrid(HID / 128, TTOK / 128);
    gemm_imma<0><<<ggrid, 256>>>(xq, wq + (size_t)0 * W_ELEMS, g, 0, qb);
    gemm_imma<0><<<ggrid, 256>>>(xq, wq + (size_t)1 * W_ELEMS, g, 1, kb);
    gemm_imma<0><<<ggrid, 256>>>(xq, wq + (size_t)2 * W_ELEMS, g, 2, vb);

    rope_kernel<<<(NB * NH * SEQ * 64) / 256, 256>>>(qb, kb);

    attn_kernel<<<dim3(SEQ / 16, NB * NH), 128>>>(qb, kb, vb, ctx);

    quant_act<<<TTOK, 256>>>(ctx, cq, g2);
    gemm_imma<1><<<ggrid, 256>>>(cq, wq + (size_t)3 * W_ELEMS, g2, 3, out);
}